// round 1
// baseline (speedup 1.0000x reference)
#include <cuda_runtime.h>
#include <cuda_bf16.h>

// Problem constants (fixed shapes from reference)
#define BATCH 8
#define CCH   64
#define DD    32
#define HH    64
#define WW    64
#define S_SPATIAL (DD*HH*WW)       // 131072 spatial positions per (b,c)
#define S4        (S_SPATIAL/4)    // 32768 float4 positions

// 8 MB scratch for reduced tensor [B, 2, D, H, W] (avg then max per batch)
__device__ float g_scratch[BATCH * 2 * S_SPATIAL];

// ---------------------------------------------------------------------------
// Kernel 1: channel-wise mean + max over C=64.
// One thread handles 4 consecutive W positions (float4). Reads 256 MB total,
// fully coalesced (warp reads 512 contiguous bytes per channel step).
// ---------------------------------------------------------------------------
__global__ __launch_bounds__(256) void reduce_mean_max_kernel(const float* __restrict__ x) {
    int idx = blockIdx.x * blockDim.x + threadIdx.x;   // over BATCH * S4
    if (idx >= BATCH * S4) return;
    int b  = idx >> 15;            // / S4
    int s4 = idx & (S4 - 1);       // % S4

    const float4* base = reinterpret_cast<const float4*>(x)
                         + (size_t)b * CCH * S4 + s4;

    float4 v = base[0];
    float4 sum = v;
    float4 mx  = v;
    #pragma unroll 8
    for (int c = 1; c < CCH; c++) {
        float4 t = base[(size_t)c * S4];
        sum.x += t.x; sum.y += t.y; sum.z += t.z; sum.w += t.w;
        mx.x = fmaxf(mx.x, t.x); mx.y = fmaxf(mx.y, t.y);
        mx.z = fmaxf(mx.z, t.z); mx.w = fmaxf(mx.w, t.w);
    }
    const float inv = 1.0f / (float)CCH;
    float4 avg = make_float4(sum.x * inv, sum.y * inv, sum.z * inv, sum.w * inv);

    float4* out_avg = reinterpret_cast<float4*>(g_scratch)
                      + (size_t)b * 2 * S4 + s4;
    float4* out_max = out_avg + S4;
    *out_avg = avg;
    *out_max = mx;
}

// ---------------------------------------------------------------------------
// Kernel 2: 3x3x3 SAME conv (2 in-ch -> 1 out-ch) + sigmoid.
// One thread computes 4 consecutive W outputs. For each of the 18 (ci,dz,dy)
// rows it loads a 6-wide register strip (1 guarded scalar + float4 + 1 guarded
// scalar) and reuses it across 3 kw taps x 4 outputs.
// ---------------------------------------------------------------------------
__global__ __launch_bounds__(256) void conv_sigmoid_kernel(const float* __restrict__ Wp,
                                                           float* __restrict__ out) {
    const int W4G = WW / 4;                         // 16 groups along W
    int idx = blockIdx.x * blockDim.x + threadIdx.x; // over BATCH*DD*HH*W4G
    if (idx >= BATCH * DD * HH * W4G) return;

    int w4 = (idx & (W4G - 1)) * 4;
    int t  = idx >> 4;
    int h  = t & (HH - 1);  t >>= 6;
    int d  = t & (DD - 1);
    int b  = t >> 5;

    // Preload 54 weights into registers (uniform -> L1 broadcast)
    float wreg[54];
    #pragma unroll
    for (int i = 0; i < 54; i++) wreg[i] = __ldg(Wp + i);

    float acc0 = 0.f, acc1 = 0.f, acc2 = 0.f, acc3 = 0.f;
    const float* sbase = g_scratch + (size_t)b * 2 * S_SPATIAL;

    #pragma unroll
    for (int ci = 0; ci < 2; ci++) {
        #pragma unroll
        for (int dz = 0; dz < 3; dz++) {
            int z = d + dz - 1;
            if (z < 0 || z >= DD) continue;
            #pragma unroll
            for (int dy = 0; dy < 3; dy++) {
                int y = h + dy - 1;
                if (y < 0 || y >= HH) continue;
                const float* row = sbase + ci * S_SPATIAL + (z * HH + y) * WW;
                float v0 = (w4 > 0)        ? row[w4 - 1] : 0.f;
                float4 m = *reinterpret_cast<const float4*>(row + w4);
                float v5 = (w4 + 4 < WW)   ? row[w4 + 4] : 0.f;
                const float* wr = wreg + (ci * 27 + dz * 9 + dy * 3);
                acc0 = fmaf(v0,  wr[0], fmaf(m.x, wr[1], fmaf(m.y, wr[2], acc0)));
                acc1 = fmaf(m.x, wr[0], fmaf(m.y, wr[1], fmaf(m.z, wr[2], acc1)));
                acc2 = fmaf(m.y, wr[0], fmaf(m.z, wr[1], fmaf(m.w, wr[2], acc2)));
                acc3 = fmaf(m.z, wr[0], fmaf(m.w, wr[1], fmaf(v5,  wr[2], acc3)));
            }
        }
    }

    float4 o;
    o.x = 1.0f / (1.0f + __expf(-acc0));
    o.y = 1.0f / (1.0f + __expf(-acc1));
    o.z = 1.0f / (1.0f + __expf(-acc2));
    o.w = 1.0f / (1.0f + __expf(-acc3));
    *reinterpret_cast<float4*>(out + (size_t)b * S_SPATIAL + (d * HH + h) * WW + w4) = o;
}

extern "C" void kernel_launch(void* const* d_in, const int* in_sizes, int n_in,
                              void* d_out, int out_size) {
    const float* x  = (const float*)d_in[0];   // [8,64,32,64,64]
    const float* Wp = (const float*)d_in[1];   // [1,2,3,3,3] = 54 floats
    float* out = (float*)d_out;                // [8,1,32,64,64]

    {
        int total = BATCH * S4;                // 262144
        int threads = 256;
        int blocks = (total + threads - 1) / threads;
        reduce_mean_max_kernel<<<blocks, threads>>>(x);
    }
    {
        int total = BATCH * DD * HH * (WW / 4); // 262144
        int threads = 256;
        int blocks = (total + threads - 1) / threads;
        conv_sigmoid_kernel<<<blocks, threads>>>(Wp, out);
    }
}

// round 3
// speedup vs baseline: 1.0780x; 1.0780x over previous
#include <cuda_runtime.h>
#include <cuda_bf16.h>

// Problem constants (fixed shapes from reference)
#define BATCH 8
#define CCH   64
#define DD    32
#define HH    64
#define WW    64
#define S_SPATIAL (DD*HH*WW)       // 131072 spatial positions per (b,c)
#define S4        (S_SPATIAL/4)    // 32768 float4 positions

// 8 MB scratch for reduced tensor [B, 2, D, H, W] (avg then max per batch)
__device__ float g_scratch[BATCH * 2 * S_SPATIAL];

// ---------------------------------------------------------------------------
// Kernel 1: channel-wise mean + max over C=64.  (unchanged — BW-bound ~6.1TB/s)
// ---------------------------------------------------------------------------
__global__ __launch_bounds__(256) void reduce_mean_max_kernel(const float* __restrict__ x) {
    int idx = blockIdx.x * blockDim.x + threadIdx.x;   // over BATCH * S4
    if (idx >= BATCH * S4) return;
    int b  = idx >> 15;            // / S4
    int s4 = idx & (S4 - 1);       // % S4

    const float4* base = reinterpret_cast<const float4*>(x)
                         + (size_t)b * CCH * S4 + s4;

    float4 v = base[0];
    float4 sum = v;
    float4 mx  = v;
    #pragma unroll 8
    for (int c = 1; c < CCH; c++) {
        float4 t = base[(size_t)c * S4];
        sum.x += t.x; sum.y += t.y; sum.z += t.z; sum.w += t.w;
        mx.x = fmaxf(mx.x, t.x); mx.y = fmaxf(mx.y, t.y);
        mx.z = fmaxf(mx.z, t.z); mx.w = fmaxf(mx.w, t.w);
    }
    const float inv = 1.0f / (float)CCH;
    float4 avg = make_float4(sum.x * inv, sum.y * inv, sum.z * inv, sum.w * inv);

    float4* out_avg = reinterpret_cast<float4*>(g_scratch)
                      + (size_t)b * 2 * S4 + s4;
    float4* out_max = out_avg + S4;
    *out_avg = avg;
    *out_max = mx;
}

// ---------------------------------------------------------------------------
// Kernel 2: 3x3x3 SAME conv (2 in-ch -> 1 out-ch) + sigmoid.
// Each thread computes a 4(D) x 4(W) output tile at fixed (b,h).
// A loaded 6-wide W-strip at depth z serves up to 3 dz taps (outputs
// od = zz - dz, compile-time). Strip loads: 2ci * 6z * 3dy = 36 per 16
// outputs = 6.75 loads/output (was 13.5). Weights: 27 regs per ci phase.
// ---------------------------------------------------------------------------
__global__ __launch_bounds__(128) void conv_sigmoid_kernel(const float* __restrict__ Wp,
                                                           float* __restrict__ out) {
    int idx = blockIdx.x * blockDim.x + threadIdx.x; // over BATCH*(DD/4)*HH*(WW/4) = 65536
    if (idx >= BATCH * (DD/4) * HH * (WW/4)) return;
    // bits: w4g[0:4], h[4:10], d4[10:13], b[13:16]
    int w4 = (idx & 15) * 4;
    int h  = (idx >> 4) & 63;
    int d0 = ((idx >> 10) & 7) * 4;
    int b  = idx >> 13;

    float acc[4][4];
    #pragma unroll
    for (int i = 0; i < 4; i++)
        #pragma unroll
        for (int j = 0; j < 4; j++) acc[i][j] = 0.f;

    const float* sbase = g_scratch + (size_t)b * 2 * S_SPATIAL;

    #pragma unroll
    for (int ci = 0; ci < 2; ci++) {
        // 27 weights for this input channel in registers
        float wreg[27];
        #pragma unroll
        for (int i = 0; i < 27; i++) wreg[i] = __ldg(Wp + ci * 27 + i);

        const float* cbase = sbase + ci * S_SPATIAL;

        #pragma unroll
        for (int zz = 0; zz < 6; zz++) {
            int z = d0 + zz - 1;
            if (z < 0 || z >= DD) continue;   // runtime only at batch-boundary tiles
            #pragma unroll
            for (int dy = 0; dy < 3; dy++) {
                int y = h + dy - 1;
                if (y < 0 || y >= HH) continue;
                const float* row = cbase + (z * HH + y) * WW + w4;
                float v0 = (w4 > 0)      ? row[-1] : 0.f;
                float4 m = *reinterpret_cast<const float4*>(row);
                float v5 = (w4 + 4 < WW) ? row[4]  : 0.f;
                #pragma unroll
                for (int dz = 0; dz < 3; dz++) {
                    const int od = zz - dz;          // compile-time per (zz,dz)
                    if (od < 0 || od >= 4) continue; // compile-time prune
                    const float* wr = wreg + dz * 9 + dy * 3;
                    acc[od][0] = fmaf(v0,  wr[0], fmaf(m.x, wr[1], fmaf(m.y, wr[2], acc[od][0])));
                    acc[od][1] = fmaf(m.x, wr[0], fmaf(m.y, wr[1], fmaf(m.z, wr[2], acc[od][1])));
                    acc[od][2] = fmaf(m.y, wr[0], fmaf(m.z, wr[1], fmaf(m.w, wr[2], acc[od][2])));
                    acc[od][3] = fmaf(m.z, wr[0], fmaf(m.w, wr[1], fmaf(v5,  wr[2], acc[od][3])));
                }
            }
        }
    }

    #pragma unroll
    for (int od = 0; od < 4; od++) {
        float4 o;
        o.x = 1.0f / (1.0f + __expf(-acc[od][0]));
        o.y = 1.0f / (1.0f + __expf(-acc[od][1]));
        o.z = 1.0f / (1.0f + __expf(-acc[od][2]));
        o.w = 1.0f / (1.0f + __expf(-acc[od][3]));
        *reinterpret_cast<float4*>(out + (size_t)b * S_SPATIAL
                                   + ((d0 + od) * HH + h) * WW + w4) = o;
    }
}

extern "C" void kernel_launch(void* const* d_in, const int* in_sizes, int n_in,
                              void* d_out, int out_size) {
    const float* x  = (const float*)d_in[0];   // [8,64,32,64,64]
    const float* Wp = (const float*)d_in[1];   // [1,2,3,3,3] = 54 floats
    float* out = (float*)d_out;                // [8,1,32,64,64]

    {
        int total = BATCH * S4;                // 262144
        int threads = 256;
        int blocks = (total + threads - 1) / threads;
        reduce_mean_max_kernel<<<blocks, threads>>>(x);
    }
    {
        int total = BATCH * (DD/4) * HH * (WW/4); // 65536
        int threads = 128;
        int blocks = (total + threads - 1) / threads;
        conv_sigmoid_kernel<<<blocks, threads>>>(Wp, out);
    }
}

// round 5
// speedup vs baseline: 1.1291x; 1.0474x over previous
#include <cuda_runtime.h>
#include <cuda_bf16.h>

// Problem constants (fixed shapes from reference)
#define BATCH 8
#define CCH   64
#define DD    32
#define HH    64
#define WW    64
#define S_SPATIAL (DD*HH*WW)       // 131072 spatial positions per (b,c)
#define S4        (S_SPATIAL/4)    // 32768 float4 positions

// 8 MB scratch for reduced tensor [B, 2, D, H, W] (avg then max per batch)
__device__ float g_scratch[BATCH * 2 * S_SPATIAL];

// ---------------------------------------------------------------------------
// Kernel 1: channel-wise mean + max over C=64.  (unchanged — ~6.35 TB/s, at HBM ceiling)
// ---------------------------------------------------------------------------
__global__ __launch_bounds__(256) void reduce_mean_max_kernel(const float* __restrict__ x) {
    int idx = blockIdx.x * blockDim.x + threadIdx.x;   // over BATCH * S4
    if (idx >= BATCH * S4) return;
    int b  = idx >> 15;            // / S4
    int s4 = idx & (S4 - 1);       // % S4

    const float4* base = reinterpret_cast<const float4*>(x)
                         + (size_t)b * CCH * S4 + s4;

    float4 v = base[0];
    float4 sum = v;
    float4 mx  = v;
    #pragma unroll 8
    for (int c = 1; c < CCH; c++) {
        float4 t = base[(size_t)c * S4];
        sum.x += t.x; sum.y += t.y; sum.z += t.z; sum.w += t.w;
        mx.x = fmaxf(mx.x, t.x); mx.y = fmaxf(mx.y, t.y);
        mx.z = fmaxf(mx.z, t.z); mx.w = fmaxf(mx.w, t.w);
    }
    const float inv = 1.0f / (float)CCH;
    float4 avg = make_float4(sum.x * inv, sum.y * inv, sum.z * inv, sum.w * inv);

    float4* out_avg = reinterpret_cast<float4*>(g_scratch)
                      + (size_t)b * 2 * S4 + s4;
    float4* out_max = out_avg + S4;
    *out_avg = avg;
    *out_max = mx;
}

// ---------------------------------------------------------------------------
// Kernel 2: smem-tiled 3x3x3 SAME conv (2ch -> 1ch) + sigmoid.
// Block tile: (b, 2 d, 8 h, full 64 w).  Smem input [2][4][10][64] with
// pre-zeroed z/y halos (no guards in compute).  Each thread: 1 (d,h), 4 w.
// Strip = LDS.128 + two width-16 shuffles for the w-halo (no scalar LDS,
// no bank conflicts).  18 unconditional iterations x 12 FMA.
// ---------------------------------------------------------------------------
#define TZ 4            // 2 d + 2 halo
#define TY 10           // 8 h + 2 halo
#define IN_ROWS (2*TZ*TY)          // 80 rows of 64 floats
#define IN_F4   (IN_ROWS*16)       // 1280 float4

__global__ __launch_bounds__(256) void conv_sigmoid_kernel(const float* __restrict__ Wp,
                                                           float* __restrict__ out) {
    __shared__ __align__(16) float sm_in[2][TZ][TY][WW];   // 20480 B
    __shared__ float sm_w[56];

    const int tid = threadIdx.x;
    const int bx  = blockIdx.x;            // 1024 blocks
    const int ht  = bx & 7;                // 8 h-tiles
    const int dt  = (bx >> 3) & 15;        // 16 d-tiles
    const int b   = bx >> 7;               // 8 batches
    const int d0  = dt * 2;
    const int h0  = ht * 8;

    // ---- cooperative load: input tile (zero-filled halos) + weights ----
    if (tid < 54) sm_w[tid] = Wp[tid];

    const float* gbase = g_scratch + (size_t)b * 2 * S_SPATIAL;
    #pragma unroll
    for (int i = 0; i < 5; i++) {
        int idx = tid + i * 256;           // 0..1279
        int w16 = idx & 15;                // float4 within row
        int rowid = idx >> 4;              // 0..79
        int y  = rowid % TY;
        int t2 = rowid / TY;               // 0..7
        int z  = t2 & 3;
        int ci = t2 >> 2;
        int gz = d0 + z - 1;
        int gy = h0 + y - 1;
        float4 v = make_float4(0.f, 0.f, 0.f, 0.f);
        if (gz >= 0 && gz < DD && gy >= 0 && gy < HH) {
            v = *reinterpret_cast<const float4*>(gbase + ci * S_SPATIAL
                                                 + (gz * HH + gy) * WW + w16 * 4);
        }
        *reinterpret_cast<float4*>(&sm_in[ci][z][y][w16 * 4]) = v;
    }
    __syncthreads();

    // ---- compute: thread -> (d_local, h_local, w4..w4+3) ----
    const int lane   = tid & 31;
    const int lane16 = lane & 15;
    const int w4     = lane16 * 4;
    const int dh     = (tid >> 5) * 2 + (lane >> 4);   // 0..15
    const int dl     = dh >> 3;                        // 0..1
    const int hl     = dh & 7;                         // 0..7

    float acc0 = 0.f, acc1 = 0.f, acc2 = 0.f, acc3 = 0.f;

    #pragma unroll
    for (int ci = 0; ci < 2; ci++) {
        float wreg[27];
        #pragma unroll
        for (int i = 0; i < 27; i++) wreg[i] = sm_w[ci * 27 + i];  // broadcast LDS

        #pragma unroll
        for (int dz = 0; dz < 3; dz++) {
            #pragma unroll
            for (int dy = 0; dy < 3; dy++) {
                float4 m = *reinterpret_cast<const float4*>(&sm_in[ci][dl + dz][hl + dy][w4]);
                float v0 = __shfl_up_sync(0xffffffffu, m.w, 1, 16);
                float v5 = __shfl_down_sync(0xffffffffu, m.x, 1, 16);
                if (lane16 == 0)  v0 = 0.f;   // w = -1  (true W boundary)
                if (lane16 == 15) v5 = 0.f;   // w = 64  (true W boundary)
                const float* wr = wreg + dz * 9 + dy * 3;
                acc0 = fmaf(v0,  wr[0], fmaf(m.x, wr[1], fmaf(m.y, wr[2], acc0)));
                acc1 = fmaf(m.x, wr[0], fmaf(m.y, wr[1], fmaf(m.z, wr[2], acc1)));
                acc2 = fmaf(m.y, wr[0], fmaf(m.z, wr[1], fmaf(m.w, wr[2], acc2)));
                acc3 = fmaf(m.z, wr[0], fmaf(m.w, wr[1], fmaf(v5,  wr[2], acc3)));
            }
        }
    }

    float4 o;
    o.x = 1.0f / (1.0f + __expf(-acc0));
    o.y = 1.0f / (1.0f + __expf(-acc1));
    o.z = 1.0f / (1.0f + __expf(-acc2));
    o.w = 1.0f / (1.0f + __expf(-acc3));
    *reinterpret_cast<float4*>(out + (size_t)b * S_SPATIAL
                               + ((d0 + dl) * HH + (h0 + hl)) * WW + w4) = o;
}

extern "C" void kernel_launch(void* const* d_in, const int* in_sizes, int n_in,
                              void* d_out, int out_size) {
    const float* x  = (const float*)d_in[0];   // [8,64,32,64,64]
    const float* Wp = (const float*)d_in[1];   // [1,2,3,3,3] = 54 floats
    float* out = (float*)d_out;                // [8,1,32,64,64]

    {
        int total = BATCH * S4;                // 262144
        int threads = 256;
        int blocks = (total + threads - 1) / threads;
        reduce_mean_max_kernel<<<blocks, threads>>>(x);
    }
    {
        int blocks = BATCH * 16 * 8;           // 1024
        conv_sigmoid_kernel<<<blocks, 256>>>(Wp, out);
    }
}